// round 5
// baseline (speedup 1.0000x reference)
#include <cuda_runtime.h>
#include <cuda_bf16.h>
#include <cstdint>

// Conv2d 3x3 s1 p1: x[256,224,224] f32, w[256,256,3,3] f32 -> out[256,224,224] f32
// Tensor-core implicit GEMM (mma.sync m16n8k16 bf16, f32 accum), 3-pass hi/lo split.
// Round 5: full-row N=224 CTA tile, 3-stage cp.async pipeline, 1 sync/stage.

#define H 224
#define W 224
#define C 256

// x copies: [kx(3)][ci(256)][yy(226)][x(224)] bf16, value = xpad[ci][yy-1][x+kx-1]
__device__ __align__(16) __nv_bfloat16 g_xh[3ull * C * 226 * 224];
__device__ __align__(16) __nv_bfloat16 g_xl[3ull * C * 226 * 224];
// weights: [s(2)][coh(2)][ky(3)][kc(24)][co(128)][j(32)] bf16, k = kc*32+j = kx*256+ci
#define WELEMS 589824  // 2*3*24*128*32
__device__ __align__(16) __nv_bfloat16 g_w[2ull * WELEMS];

// ---------------- prep ----------------
__global__ void prep_w_kernel(const float* __restrict__ w) {
    int i = blockIdx.x * blockDim.x + threadIdx.x;
    if (i >= WELEMS) return;
    int j    = i & 31;
    int co   = (i >> 5) & 127;
    int hi12 = i >> 12;
    int kc   = hi12 % 24;
    int t    = hi12 / 24;
    int ky   = t % 3;
    int coh  = t / 3;
    int k  = kc * 32 + j;
    int kx = k >> 8;
    int ci = k & 255;
    float v = w[(((coh * 128 + co) * C + ci) * 3 + ky) * 3 + kx];
    __nv_bfloat16 hi = __float2bfloat16(v);
    __nv_bfloat16 lo = __float2bfloat16(v - __bfloat162float(hi));
    g_w[i] = hi;
    g_w[WELEMS + i] = lo;
}

__global__ void prep_x_kernel(const float* __restrict__ x) {
    int yy = blockIdx.x;    // 0..225
    int ci = blockIdx.y;    // 0..255
    int xi = threadIdx.x;   // 0..223
    int ys = yy - 1;
#pragma unroll
    for (int kx = 0; kx < 3; ++kx) {
        int xs = xi + kx - 1;
        float v = 0.0f;
        if ((unsigned)ys < 224u && (unsigned)xs < 224u)
            v = x[(ci * H + ys) * W + xs];
        __nv_bfloat16 hi = __float2bfloat16(v);
        __nv_bfloat16 lo = __float2bfloat16(v - __bfloat162float(hi));
        size_t o = (((size_t)kx * C + ci) * 226 + yy) * 224 + xi;
        g_xh[o] = hi;
        g_xl[o] = lo;
    }
}

// ---------------- conv mainloop ----------------
__device__ __forceinline__ uint32_t smem_u32(const void* p) {
    uint32_t a;
    asm("{ .reg .u64 t; cvta.to.shared.u64 t, %1; cvt.u32.u64 %0, t; }" : "=r"(a) : "l"(p));
    return a;
}
__device__ __forceinline__ void cp16(uint32_t dst, const void* src) {
    asm volatile("cp.async.cg.shared.global [%0], [%1], 16;" :: "r"(dst), "l"(src) : "memory");
}
__device__ __forceinline__ void cp_commit() {
    asm volatile("cp.async.commit_group;" ::: "memory");
}
__device__ __forceinline__ void ldsm_x4(uint32_t* r, uint32_t a) {
    asm volatile("ldmatrix.sync.aligned.m8n8.x4.shared.b16 {%0,%1,%2,%3}, [%4];"
                 : "=r"(r[0]), "=r"(r[1]), "=r"(r[2]), "=r"(r[3]) : "r"(a));
}
__device__ __forceinline__ void ldsm_x2t(uint32_t* r, uint32_t a) {
    asm volatile("ldmatrix.sync.aligned.m8n8.x2.trans.shared.b16 {%0,%1}, [%2];"
                 : "=r"(r[0]), "=r"(r[1]) : "r"(a));
}
__device__ __forceinline__ void mma16816(float* d, const uint32_t* a, const uint32_t* b) {
    asm volatile(
        "mma.sync.aligned.m16n8k16.row.col.f32.bf16.bf16.f32 "
        "{%0,%1,%2,%3}, {%4,%5,%6,%7}, {%8,%9}, {%0,%1,%2,%3};"
        : "+f"(d[0]), "+f"(d[1]), "+f"(d[2]), "+f"(d[3])
        : "r"(a[0]), "r"(a[1]), "r"(a[2]), "r"(a[3]), "r"(b[0]), "r"(b[1]));
}

#define A_STRIDE 80             // 64B data + pad, conflict-free under ldsm
#define B_STRIDE 464            // 448B data + pad, conflict-free under ldsm
#define A_BYTES  (128 * A_STRIDE)   // 10240
#define B_BYTES  (32 * B_STRIDE)    // 14848
#define STAGE_BYTES (A_BYTES + B_BYTES)   // 25088
#define NBUF 3
#define SMEM_SZ (NBUF * STAGE_BYTES)      // 75264
#define NSTAGE 216              // 3 pass * 3 ky * 24 kc

__device__ __forceinline__ void load_stage(int idx, uint32_t sbase, int tid,
                                           int coh, int y) {
    int pass = idx / 72;
    int r = idx - pass * 72;
    int ky = r / 24;
    int kc = r - ky * 24;
    const __nv_bfloat16* wsrc = g_w + (pass == 2 ? WELEMS : 0)
                              + (((size_t)(coh * 3 + ky) * 24 + kc) << 12);
    const __nv_bfloat16* xarr = (pass == 1) ? g_xl : g_xh;
    int kx  = kc >> 3;
    int cib = (kc & 7) * 32;
    // A: 512 x 16B, contiguous src (2 per thread)
#pragma unroll
    for (int v = tid; v < 512; v += 256) {
        cp16(sbase + (v >> 2) * A_STRIDE + (v & 3) * 16, (const char*)wsrc + v * 16);
    }
    // B: 896 x 16B (3.5 per thread)
    uint32_t bbase = sbase + A_BYTES;
    for (int v = tid; v < 896; v += 256) {
        int row = v / 14;          // 2 gmem rows per 28 chunks -> v/14 half-rows
        int cv  = v - row * 14;    // 0..13 (16B chunks within half-row)
        int grow = row >> 1;       // 0..31 (ci within chunk)
        int half = row & 1;        // which 224B half of the 448B row
        size_t se = (((size_t)(kx * C + cib + grow)) * 226 + (y + ky)) * 224 + half * 112;
        cp16(bbase + grow * B_STRIDE + half * 224 + cv * 16,
             (const char*)xarr + se * 2 + cv * 16);
    }
}

__global__ __launch_bounds__(256, 1) void conv_mma_kernel(float* __restrict__ out) {
    extern __shared__ __align__(16) unsigned char smbuf[];
    const uint32_t sb = smem_u32(smbuf);
    const int tid  = threadIdx.x;
    const int lane = tid & 31;
    const int wid  = tid >> 5;
    const int wm   = wid & 1;     // 2 M-warps: 64 co each
    const int wn   = wid >> 1;    // 4 N-warps: 56 px each
    const int coh  = blockIdx.x;
    const int y    = blockIdx.y;

    float acc[4][7][4];
#pragma unroll
    for (int m = 0; m < 4; ++m)
#pragma unroll
        for (int n = 0; n < 7; ++n)
#pragma unroll
            for (int q = 0; q < 4; ++q) acc[m][n][q] = 0.0f;

    load_stage(0, sb, tid, coh, y);
    cp_commit();
    load_stage(1, sb + STAGE_BYTES, tid, coh, y);
    cp_commit();

    int buf = 0;
    for (int i = 0; i < NSTAGE; ++i) {
        asm volatile("cp.async.wait_group 1;" ::: "memory");
        __syncthreads();
        if (i + 2 < NSTAGE) {
            int nb = buf + 2; if (nb >= NBUF) nb -= NBUF;
            load_stage(i + 2, sb + nb * STAGE_BYTES, tid, coh, y);
        }
        cp_commit();   // one group per stage (possibly empty near the end)

        const uint32_t As = sb + buf * STAGE_BYTES;
        const uint32_t Bs = As + A_BYTES;
        uint32_t aA[4], aB[7];
#pragma unroll
        for (int m = 0; m < 4; ++m)
            aA[m] = As + (wm * 64 + m * 16 + (lane & 15)) * A_STRIDE + (lane >> 4) * 16;
#pragma unroll
        for (int n = 0; n < 7; ++n)
            aB[n] = Bs + (lane & 15) * B_STRIDE + wn * 112 + n * 16;

#pragma unroll
        for (int ks = 0; ks < 2; ++ks) {
            uint32_t a[4][4], b[7][2];
#pragma unroll
            for (int m = 0; m < 4; ++m) ldsm_x4(a[m], aA[m] + ks * 32);
#pragma unroll
            for (int n = 0; n < 7; ++n) ldsm_x2t(b[n], aB[n] + ks * 16 * B_STRIDE);
#pragma unroll
            for (int m = 0; m < 4; ++m)
#pragma unroll
                for (int n = 0; n < 7; ++n) mma16816(acc[m][n], a[m], b[n]);
        }

        ++buf; if (buf >= NBUF) buf = 0;
    }

    // epilogue: write D (f32), warp covers 64co x 56px
    const int rq = lane >> 2;
    const int cq = (lane & 3) * 2;
#pragma unroll
    for (int m = 0; m < 4; ++m) {
#pragma unroll
        for (int n = 0; n < 7; ++n) {
            int co = coh * 128 + wm * 64 + m * 16 + rq;
            int xx = wn * 56 + n * 8 + cq;
            float* p0 = out + ((size_t)co * H + y) * W + xx;
            float* p1 = out + ((size_t)(co + 8) * H + y) * W + xx;
            *(float2*)p0 = make_float2(acc[m][n][0], acc[m][n][1]);
            *(float2*)p1 = make_float2(acc[m][n][2], acc[m][n][3]);
        }
    }
}

extern "C" void kernel_launch(void* const* d_in, const int* in_sizes, int n_in,
                              void* d_out, int out_size) {
    const float* x = (const float*)d_in[0];   // [1,256,224,224]
    const float* w = (const float*)d_in[1];   // [256,256,3,3]
    float* out = (float*)d_out;               // [256,224,224]
    (void)in_sizes; (void)n_in; (void)out_size;

    prep_w_kernel<<<(WELEMS + 255) / 256, 256>>>(w);
    prep_x_kernel<<<dim3(226, 256), 224>>>(x);

    static int smem_set = 0;
    if (!smem_set) {
        cudaFuncSetAttribute(conv_mma_kernel,
                             cudaFuncAttributeMaxDynamicSharedMemorySize, SMEM_SZ);
        smem_set = 1;
    }
    conv_mma_kernel<<<dim3(2, H), 256, SMEM_SZ>>>(out);
}

// round 6
// speedup vs baseline: 2.6340x; 2.6340x over previous
#include <cuda_runtime.h>
#include <cuda_fp16.h>
#include <cstdint>

// Conv2d 3x3 s1 p1: x[256,224,224] f32, w[256,256,3,3] f32 -> out[256,224,224] f32
// Tensor-core implicit GEMM, mma.sync m16n8k16 fp16 -> f32 accumulate.
// Round 6: SINGLE PASS fp16 (products exact in f32; only input-quantization
// error ~2^-11 -> global rel err ~4e-4). 3x fewer MACs than 3-pass bf16 split.

#define H 224
#define W 224
#define C 256

// x copy: [kx(3)][ci(256)][yy(226)][x(224)] fp16, value = xpad[ci][yy-1][x+kx-1]
__device__ __align__(16) __half g_x[3ull * C * 226 * 224];
// weights: [coh(2)][ky(3)][kc(24)][co(128)][j(32)] fp16, k = kc*32+j = kx*256+ci
#define WELEMS 589824  // 2*3*24*128*32
__device__ __align__(16) __half g_w[WELEMS];

// ---------------- prep ----------------
__global__ void prep_w_kernel(const float* __restrict__ w) {
    int i = blockIdx.x * blockDim.x + threadIdx.x;
    if (i >= WELEMS) return;
    int j    = i & 31;
    int co   = (i >> 5) & 127;
    int hi12 = i >> 12;
    int kc   = hi12 % 24;
    int t    = hi12 / 24;
    int ky   = t % 3;
    int coh  = t / 3;
    int k  = kc * 32 + j;
    int kx = k >> 8;
    int ci = k & 255;
    float v = w[(((coh * 128 + co) * C + ci) * 3 + ky) * 3 + kx];
    g_w[i] = __float2half_rn(v);
}

__global__ void prep_x_kernel(const float* __restrict__ x) {
    int yy = blockIdx.x;    // 0..225
    int ci = blockIdx.y;    // 0..255
    int xi = threadIdx.x;   // 0..223
    int ys = yy - 1;
#pragma unroll
    for (int kx = 0; kx < 3; ++kx) {
        int xs = xi + kx - 1;
        float v = 0.0f;
        if ((unsigned)ys < 224u && (unsigned)xs < 224u)
            v = x[(ci * H + ys) * W + xs];
        size_t o = (((size_t)kx * C + ci) * 226 + yy) * 224 + xi;
        g_x[o] = __float2half_rn(v);
    }
}

// ---------------- conv mainloop ----------------
__device__ __forceinline__ uint32_t smem_u32(const void* p) {
    uint32_t a;
    asm("{ .reg .u64 t; cvta.to.shared.u64 t, %1; cvt.u32.u64 %0, t; }" : "=r"(a) : "l"(p));
    return a;
}
__device__ __forceinline__ void cp16(uint32_t dst, const void* src) {
    asm volatile("cp.async.cg.shared.global [%0], [%1], 16;" :: "r"(dst), "l"(src) : "memory");
}
__device__ __forceinline__ void cp_commit() {
    asm volatile("cp.async.commit_group;" ::: "memory");
}
__device__ __forceinline__ void ldsm_x4(uint32_t* r, uint32_t a) {
    asm volatile("ldmatrix.sync.aligned.m8n8.x4.shared.b16 {%0,%1,%2,%3}, [%4];"
                 : "=r"(r[0]), "=r"(r[1]), "=r"(r[2]), "=r"(r[3]) : "r"(a));
}
__device__ __forceinline__ void ldsm_x2t(uint32_t* r, uint32_t a) {
    asm volatile("ldmatrix.sync.aligned.m8n8.x2.trans.shared.b16 {%0,%1}, [%2];"
                 : "=r"(r[0]), "=r"(r[1]) : "r"(a));
}
__device__ __forceinline__ void mma16816(float* d, const uint32_t* a, const uint32_t* b) {
    asm volatile(
        "mma.sync.aligned.m16n8k16.row.col.f32.f16.f16.f32 "
        "{%0,%1,%2,%3}, {%4,%5,%6,%7}, {%8,%9}, {%0,%1,%2,%3};"
        : "+f"(d[0]), "+f"(d[1]), "+f"(d[2]), "+f"(d[3])
        : "r"(a[0]), "r"(a[1]), "r"(a[2]), "r"(a[3]), "r"(b[0]), "r"(b[1]));
}

#define A_BYTES 10240           // 128 rows * 80B (64 used)
#define B_BYTES 7680            // 32 rows * 240B (224 used)
#define STAGE_BYTES (A_BYTES + B_BYTES)
#define NSTAGE 72               // 3 ky * 24 kc, single pass

__device__ __forceinline__ void load_stage(int idx, uint32_t sbase, int tid,
                                           int coh, int xh, int y) {
    int ky = idx / 24;
    int kc = idx - ky * 24;
    const __half* wsrc = g_w + (((size_t)(coh * 3 + ky) * 24 + kc) << 12);
    int kx  = kc >> 3;
    int cib = (kc & 7) * 32;
    // A: 512 x 16B, contiguous src
#pragma unroll
    for (int v = tid; v < 512; v += 256) {
        cp16(sbase + (v >> 2) * 80 + (v & 3) * 16, (const char*)wsrc + v * 16);
    }
    // B: 448 x 16B
    uint32_t bbase = sbase + A_BYTES;
    for (int v = tid; v < 448; v += 256) {
        int row = v / 14;
        int cv  = v - row * 14;
        size_t se = (((size_t)(kx * C + cib + row)) * 226 + (y + ky)) * 224 + xh * 112;
        cp16(bbase + row * 240 + cv * 16, (const char*)g_x + se * 2 + cv * 16);
    }
}

__global__ __launch_bounds__(256, 2) void conv_mma_kernel(float* __restrict__ out) {
    __shared__ __align__(16) unsigned char smbuf[2 * STAGE_BYTES];   // 35840 B
    const uint32_t sb = smem_u32(smbuf);
    const int tid  = threadIdx.x;
    const int lane = tid & 31;
    const int wid  = tid >> 5;
    const int wm   = wid & 3;     // warp M index (co)
    const int wn   = wid >> 2;    // warp N index (px)
    const int xh   = blockIdx.x & 1;
    const int coh  = blockIdx.x >> 1;
    const int y    = blockIdx.y;

    float acc[2][7][4];
#pragma unroll
    for (int m = 0; m < 2; ++m)
#pragma unroll
        for (int n = 0; n < 7; ++n)
#pragma unroll
            for (int q = 0; q < 4; ++q) acc[m][n][q] = 0.0f;

    load_stage(0, sb, tid, coh, xh, y);
    cp_commit();

    for (int i = 0; i < NSTAGE; ++i) {
        if (i + 1 < NSTAGE) {
            load_stage(i + 1, sb + ((i + 1) & 1) * STAGE_BYTES, tid, coh, xh, y);
            cp_commit();
            asm volatile("cp.async.wait_group 1;" ::: "memory");
        } else {
            asm volatile("cp.async.wait_group 0;" ::: "memory");
        }
        __syncthreads();

        const uint32_t As = sb + (i & 1) * STAGE_BYTES;
        const uint32_t Bs = As + A_BYTES;
        uint32_t aA[2], aB[7];
#pragma unroll
        for (int m = 0; m < 2; ++m)
            aA[m] = As + (wm * 32 + m * 16 + (lane & 15)) * 80 + (lane >> 4) * 16;
#pragma unroll
        for (int n = 0; n < 7; ++n)
            aB[n] = Bs + (lane & 15) * 240 + wn * 112 + n * 16;

#pragma unroll
        for (int ks = 0; ks < 2; ++ks) {
            uint32_t a[2][4], b[7][2];
#pragma unroll
            for (int m = 0; m < 2; ++m) ldsm_x4(a[m], aA[m] + ks * 32);
#pragma unroll
            for (int n = 0; n < 7; ++n) ldsm_x2t(b[n], aB[n] + ks * 16 * 240);
#pragma unroll
            for (int m = 0; m < 2; ++m)
#pragma unroll
                for (int n = 0; n < 7; ++n) mma16816(acc[m][n], a[m], b[n]);
        }
        __syncthreads();
    }

    // epilogue: write D tiles (f32)
    const int rq = lane >> 2;
    const int cq = (lane & 3) * 2;
#pragma unroll
    for (int m = 0; m < 2; ++m) {
#pragma unroll
        for (int n = 0; n < 7; ++n) {
            int co = coh * 128 + wm * 32 + m * 16 + rq;
            int xx = xh * 112 + wn * 56 + n * 8 + cq;
            float* p0 = out + ((size_t)co * H + y) * W + xx;
            float* p1 = out + ((size_t)(co + 8) * H + y) * W + xx;
            *(float2*)p0 = make_float2(acc[m][n][0], acc[m][n][1]);
            *(float2*)p1 = make_float2(acc[m][n][2], acc[m][n][3]);
        }
    }
}

extern "C" void kernel_launch(void* const* d_in, const int* in_sizes, int n_in,
                              void* d_out, int out_size) {
    const float* x = (const float*)d_in[0];   // [1,256,224,224]
    const float* w = (const float*)d_in[1];   // [256,256,3,3]
    float* out = (float*)d_out;               // [256,224,224]
    (void)in_sizes; (void)n_in; (void)out_size;

    prep_w_kernel<<<(WELEMS + 255) / 256, 256>>>(w);
    prep_x_kernel<<<dim3(226, 256), 224>>>(x);

    // grid.x: {xh, coh}; grid.y: output row y
    conv_mma_kernel<<<dim3(4, H), 256>>>(out);
}

// round 7
// speedup vs baseline: 3.3739x; 1.2809x over previous
#include <cuda_runtime.h>
#include <cuda_fp16.h>
#include <cstdint>

// Conv2d 3x3 s1 p1: x[256,224,224] f32, w[256,256,3,3] f32 -> out[256,224,224] f32
// Round 7: Winograd F(2x2,3x3) on fp16 tensor cores (mma.sync m16n8k16, f32 acc).
//   16 component GEMMs: M_k[co,tile] = sum_ci W'_k[co,ci] * U_k[ci,tile]
//   MACs: 13.2G vs 29.6G direct (2.25x reduction; legacy-HMMA pipe is the bound).
//   Transforms computed in fp32; U, W', M stored fp16.

#define H 224
#define W 224
#define C 256
#define NTILE 12544          // 112*112 output tiles of 2x2
#define TW 112               // tiles per image row

// U: [k(16)][ci(256)][tile(12544)] fp16  (103 MB)
__device__ __align__(16) __half g_U[16ull * C * NTILE];
// M: [k(16)][co(256)][tile(12544)] fp16  (103 MB)
__device__ __align__(16) __half g_M[16ull * C * NTILE];
// W': [k(16)][coh(2)][kc(8)][co(128)][j(32)] fp16, ci = kc*32+j  (2 MB)
__device__ __align__(16) __half g_Wt[16ull * 2 * 8 * 128 * 32];

// ---------------- weight transform: W' = G w G^T ----------------
__global__ void wino_w_kernel(const float* __restrict__ w) {
    int i = blockIdx.x * blockDim.x + threadIdx.x;   // 65536 = co*ci
    if (i >= C * C) return;
    int ci = i & 255;
    int co = i >> 8;
    float g[3][3];
#pragma unroll
    for (int r = 0; r < 3; ++r)
#pragma unroll
        for (int c = 0; c < 3; ++c)
            g[r][c] = w[((co * C + ci) * 3 + r) * 3 + c];
    float t[4][3];
#pragma unroll
    for (int c = 0; c < 3; ++c) {
        t[0][c] = g[0][c];
        t[1][c] = 0.5f * (g[0][c] + g[1][c] + g[2][c]);
        t[2][c] = 0.5f * (g[0][c] - g[1][c] + g[2][c]);
        t[3][c] = g[2][c];
    }
    float u[4][4];
#pragma unroll
    for (int r = 0; r < 4; ++r) {
        u[r][0] = t[r][0];
        u[r][1] = 0.5f * (t[r][0] + t[r][1] + t[r][2]);
        u[r][2] = 0.5f * (t[r][0] - t[r][1] + t[r][2]);
        u[r][3] = t[r][2];
    }
    int coh = co >> 7, col = co & 127, kc = ci >> 5, j = ci & 31;
#pragma unroll
    for (int k = 0; k < 16; ++k)
        g_Wt[((((size_t)(k * 2 + coh) * 8 + kc) * 128 + col) << 5) + j] =
            __float2half_rn(u[k >> 2][k & 3]);
}

// ---------------- input transform: U = B^T d B ----------------
__global__ void wino_in_kernel(const float* __restrict__ x) {
    int t = blockIdx.x * 128 + threadIdx.x;    // 0..12543, grid.x = 98
    int ci = blockIdx.y;
    int ty = t / TW, tx = t - ty * TW;
    int y0 = 2 * ty - 1, x0 = 2 * tx - 1;
    const float* xp = x + (size_t)ci * H * W;
    float d[4][4];
#pragma unroll
    for (int r = 0; r < 4; ++r)
#pragma unroll
        for (int c = 0; c < 4; ++c) {
            int yy = y0 + r, xx = x0 + c;
            d[r][c] = ((unsigned)yy < 224u && (unsigned)xx < 224u)
                          ? xp[yy * W + xx] : 0.0f;
        }
    float tr[4][4];
#pragma unroll
    for (int c = 0; c < 4; ++c) {
        tr[0][c] = d[0][c] - d[2][c];
        tr[1][c] = d[1][c] + d[2][c];
        tr[2][c] = d[2][c] - d[1][c];
        tr[3][c] = d[1][c] - d[3][c];
    }
    float u[4][4];
#pragma unroll
    for (int r = 0; r < 4; ++r) {
        u[r][0] = tr[r][0] - tr[r][2];
        u[r][1] = tr[r][1] + tr[r][2];
        u[r][2] = tr[r][2] - tr[r][1];
        u[r][3] = tr[r][1] - tr[r][3];
    }
#pragma unroll
    for (int k = 0; k < 16; ++k)
        g_U[(size_t)(k * C + ci) * NTILE + t] = __float2half_rn(u[k >> 2][k & 3]);
}

// ---------------- batched component GEMMs ----------------
__device__ __forceinline__ uint32_t smem_u32(const void* p) {
    uint32_t a;
    asm("{ .reg .u64 t; cvta.to.shared.u64 t, %1; cvt.u32.u64 %0, t; }" : "=r"(a) : "l"(p));
    return a;
}
__device__ __forceinline__ void cp16(uint32_t dst, const void* src) {
    asm volatile("cp.async.cg.shared.global [%0], [%1], 16;" :: "r"(dst), "l"(src) : "memory");
}
__device__ __forceinline__ void cp_commit() {
    asm volatile("cp.async.commit_group;" ::: "memory");
}
__device__ __forceinline__ void ldsm_x4(uint32_t* r, uint32_t a) {
    asm volatile("ldmatrix.sync.aligned.m8n8.x4.shared.b16 {%0,%1,%2,%3}, [%4];"
                 : "=r"(r[0]), "=r"(r[1]), "=r"(r[2]), "=r"(r[3]) : "r"(a));
}
__device__ __forceinline__ void ldsm_x2t(uint32_t* r, uint32_t a) {
    asm volatile("ldmatrix.sync.aligned.m8n8.x2.trans.shared.b16 {%0,%1}, [%2];"
                 : "=r"(r[0]), "=r"(r[1]) : "r"(a));
}
__device__ __forceinline__ void mma16816(float* d, const uint32_t* a, const uint32_t* b) {
    asm volatile(
        "mma.sync.aligned.m16n8k16.row.col.f32.f16.f16.f32 "
        "{%0,%1,%2,%3}, {%4,%5,%6,%7}, {%8,%9}, {%0,%1,%2,%3};"
        : "+f"(d[0]), "+f"(d[1]), "+f"(d[2]), "+f"(d[3])
        : "r"(a[0]), "r"(a[1]), "r"(a[2]), "r"(a[3]), "r"(b[0]), "r"(b[1]));
}

#define A_BYTES 10240           // 128 rows * 80B (64 used)
#define B_BYTES 7680            // 32 rows * 240B (224 used = 112 tiles fp16)
#define STAGE_BYTES (A_BYTES + B_BYTES)
#define NSTAGE 8                // K = 256 = 8 * 32

__device__ __forceinline__ void load_stage(int kc, uint32_t sbase, int tid,
                                           int k, int coh, int tb) {
    const __half* wsrc = g_Wt + (((size_t)(k * 2 + coh) * 8 + kc) << 12);
    // A: 512 x 16B contiguous
#pragma unroll
    for (int v = tid; v < 512; v += 256) {
        cp16(sbase + (v >> 2) * 80 + (v & 3) * 16, (const char*)wsrc + v * 16);
    }
    // B: 448 x 16B — rows are ci, 112 tiles each
    uint32_t bbase = sbase + A_BYTES;
    const __half* usrc = g_U + (size_t)(k * C + kc * 32) * NTILE + tb * 112;
    for (int v = tid; v < 448; v += 256) {
        int row = v / 14;
        int cv  = v - row * 14;
        cp16(bbase + row * 240 + cv * 16,
             (const char*)(usrc + (size_t)row * NTILE) + cv * 16);
    }
}

__global__ __launch_bounds__(256, 2) void wino_gemm_kernel() {
    __shared__ __align__(16) unsigned char smbuf[2 * STAGE_BYTES];   // 35840 B
    const uint32_t sb = smem_u32(smbuf);
    const int tid  = threadIdx.x;
    const int lane = tid & 31;
    const int wid  = tid >> 5;
    const int wm   = wid & 3;       // 4 M-warps x 32 co
    const int wn   = wid >> 2;      // 2 N-warps x 56 tiles
    const int tb   = blockIdx.x;    // 0..111 (112-tile blocks)
    const int k    = blockIdx.y >> 1;
    const int coh  = blockIdx.y & 1;

    float acc[2][7][4];
#pragma unroll
    for (int m = 0; m < 2; ++m)
#pragma unroll
        for (int n = 0; n < 7; ++n)
#pragma unroll
            for (int q = 0; q < 4; ++q) acc[m][n][q] = 0.0f;

    load_stage(0, sb, tid, k, coh, tb);
    cp_commit();

    for (int i = 0; i < NSTAGE; ++i) {
        if (i + 1 < NSTAGE) {
            load_stage(i + 1, sb + ((i + 1) & 1) * STAGE_BYTES, tid, k, coh, tb);
            cp_commit();
            asm volatile("cp.async.wait_group 1;" ::: "memory");
        } else {
            asm volatile("cp.async.wait_group 0;" ::: "memory");
        }
        __syncthreads();

        const uint32_t As = sb + (i & 1) * STAGE_BYTES;
        const uint32_t Bs = As + A_BYTES;
        uint32_t aA[2], aB[7];
#pragma unroll
        for (int m = 0; m < 2; ++m)
            aA[m] = As + (wm * 32 + m * 16 + (lane & 15)) * 80 + (lane >> 4) * 16;
#pragma unroll
        for (int n = 0; n < 7; ++n)
            aB[n] = Bs + (lane & 15) * 240 + wn * 112 + n * 16;

#pragma unroll
        for (int ks = 0; ks < 2; ++ks) {
            uint32_t a[2][4], b[7][2];
#pragma unroll
            for (int m = 0; m < 2; ++m) ldsm_x4(a[m], aA[m] + ks * 32);
#pragma unroll
            for (int n = 0; n < 7; ++n) ldsm_x2t(b[n], aB[n] + ks * 16 * 240);
#pragma unroll
            for (int m = 0; m < 2; ++m)
#pragma unroll
                for (int n = 0; n < 7; ++n) mma16816(acc[m][n], a[m], b[n]);
        }
        __syncthreads();
    }

    // epilogue: write M_k fp16
    const int rq = lane >> 2;
    const int cq = (lane & 3) * 2;
#pragma unroll
    for (int m = 0; m < 2; ++m) {
#pragma unroll
        for (int n = 0; n < 7; ++n) {
            int co  = coh * 128 + wm * 32 + m * 16 + rq;
            int col = wn * 56 + n * 8 + cq;
            size_t base = (size_t)(k * C + co) * NTILE + tb * 112 + col;
            *(__half2*)&g_M[base] =
                __floats2half2_rn(acc[m][n][0], acc[m][n][1]);
            *(__half2*)&g_M[base + 8ull * NTILE] =
                __floats2half2_rn(acc[m][n][2], acc[m][n][3]);
        }
    }
}

// ---------------- inverse transform: y = A^T M A ----------------
__global__ void wino_out_kernel(float* __restrict__ out) {
    int t = blockIdx.x * 256 + threadIdx.x;    // grid.x = 49
    int co = blockIdx.y;
    int ty = t / TW, tx = t - ty * TW;
    float m[4][4];
#pragma unroll
    for (int k = 0; k < 16; ++k)
        m[k >> 2][k & 3] = __half2float(g_M[(size_t)(k * C + co) * NTILE + t]);
    float r0[4], r1[4];
#pragma unroll
    for (int c = 0; c < 4; ++c) {
        r0[c] = m[0][c] + m[1][c] + m[2][c];
        r1[c] = m[1][c] - m[2][c] - m[3][c];
    }
    float y00 = r0[0] + r0[1] + r0[2];
    float y01 = r0[1] - r0[2] - r0[3];
    float y10 = r1[0] + r1[1] + r1[2];
    float y11 = r1[1] - r1[2] - r1[3];
    float* p = out + ((size_t)co * H + 2 * ty) * W + 2 * tx;
    *(float2*)p       = make_float2(y00, y01);
    *(float2*)(p + W) = make_float2(y10, y11);
}

extern "C" void kernel_launch(void* const* d_in, const int* in_sizes, int n_in,
                              void* d_out, int out_size) {
    const float* x = (const float*)d_in[0];   // [1,256,224,224]
    const float* w = (const float*)d_in[1];   // [256,256,3,3]
    float* out = (float*)d_out;               // [256,224,224]
    (void)in_sizes; (void)n_in; (void)out_size;

    wino_w_kernel<<<(C * C + 255) / 256, 256>>>(w);
    wino_in_kernel<<<dim3(98, C), 128>>>(x);
    wino_gemm_kernel<<<dim3(TW, 32), 256>>>();      // 112 tile-blocks x (16k * 2coh)
    wino_out_kernel<<<dim3(49, C), 256>>>(out);
}

// round 8
// speedup vs baseline: 3.6189x; 1.0726x over previous
#include <cuda_runtime.h>
#include <cuda_fp16.h>
#include <cstdint>

// Conv2d 3x3 s1 p1: x[256,224,224] f32, w[256,256,3,3] f32 -> out[256,224,224] f32
// Winograd F(2x2,3x3) on fp16 tensor cores (mma.sync m16n8k16, f32 acc).
// Round 8: 2-tile-wide transforms (vectorized gmem), 4-stage GEMM pipeline.

#define H 224
#define W 224
#define C 256
#define NTILE 12544          // 112*112 output tiles of 2x2
#define TW 112               // tiles per image row

// U: [k(16)][ci(256)][tile(12544)] fp16  (103 MB)
__device__ __align__(16) __half g_U[16ull * C * NTILE];
// M: [k(16)][co(256)][tile(12544)] fp16  (103 MB)
__device__ __align__(16) __half g_M[16ull * C * NTILE];
// W': [k(16)][coh(2)][kc(8)][co(128)][j(32)] fp16, ci = kc*32+j  (2 MB)
__device__ __align__(16) __half g_Wt[16ull * 2 * 8 * 128 * 32];

// ---------------- weight transform: W' = G w G^T ----------------
__global__ void wino_w_kernel(const float* __restrict__ w) {
    int i = blockIdx.x * blockDim.x + threadIdx.x;   // 65536 = co*ci
    if (i >= C * C) return;
    int ci = i & 255;
    int co = i >> 8;
    float g[3][3];
#pragma unroll
    for (int r = 0; r < 3; ++r)
#pragma unroll
        for (int c = 0; c < 3; ++c)
            g[r][c] = w[((co * C + ci) * 3 + r) * 3 + c];
    float t[4][3];
#pragma unroll
    for (int c = 0; c < 3; ++c) {
        t[0][c] = g[0][c];
        t[1][c] = 0.5f * (g[0][c] + g[1][c] + g[2][c]);
        t[2][c] = 0.5f * (g[0][c] - g[1][c] + g[2][c]);
        t[3][c] = g[2][c];
    }
    float u[4][4];
#pragma unroll
    for (int r = 0; r < 4; ++r) {
        u[r][0] = t[r][0];
        u[r][1] = 0.5f * (t[r][0] + t[r][1] + t[r][2]);
        u[r][2] = 0.5f * (t[r][0] - t[r][1] + t[r][2]);
        u[r][3] = t[r][2];
    }
    int coh = co >> 7, col = co & 127, kc = ci >> 5, j = ci & 31;
#pragma unroll
    for (int k = 0; k < 16; ++k)
        g_Wt[((((size_t)(k * 2 + coh) * 8 + kc) * 128 + col) << 5) + j] =
            __float2half_rn(u[k >> 2][k & 3]);
}

// ---------------- input transform: U = B^T d B, 2 tiles per thread ----------
__global__ void wino_in_kernel(const float* __restrict__ x) {
    int p = blockIdx.x * 128 + threadIdx.x;    // 0..6271 tile-pairs, grid.x = 49
    int ci = blockIdx.y;
    int ty = p / 56, px = p - ty * 56;
    int tx0 = px * 2;
    int y0 = 2 * ty - 1, x0 = 2 * tx0 - 1;
    const float* xp = x + (size_t)ci * H * W;
    // 4x6 input patch covers both tiles (cols 0-3 and 2-5)
    float d[4][6];
#pragma unroll
    for (int r = 0; r < 4; ++r) {
        int yy = y0 + r;
        bool yok = (unsigned)yy < 224u;
        const float* row = xp + yy * W;
#pragma unroll
        for (int c = 0; c < 6; ++c) {
            int xx = x0 + c;
            d[r][c] = (yok && (unsigned)xx < 224u) ? row[xx] : 0.0f;
        }
    }
    // row transform shared across both tiles (all 6 cols)
    float tr[4][6];
#pragma unroll
    for (int c = 0; c < 6; ++c) {
        tr[0][c] = d[0][c] - d[2][c];
        tr[1][c] = d[1][c] + d[2][c];
        tr[2][c] = d[2][c] - d[1][c];
        tr[3][c] = d[1][c] - d[3][c];
    }
    size_t t0 = (size_t)ty * TW + tx0;
#pragma unroll
    for (int r = 0; r < 4; ++r) {
        float ua[4], ub[4];
        ua[0] = tr[r][0] - tr[r][2];
        ua[1] = tr[r][1] + tr[r][2];
        ua[2] = tr[r][2] - tr[r][1];
        ua[3] = tr[r][1] - tr[r][3];
        ub[0] = tr[r][2] - tr[r][4];
        ub[1] = tr[r][3] + tr[r][4];
        ub[2] = tr[r][4] - tr[r][3];
        ub[3] = tr[r][3] - tr[r][5];
#pragma unroll
        for (int c = 0; c < 4; ++c) {
            int k = r * 4 + c;
            *(__half2*)&g_U[(size_t)(k * C + ci) * NTILE + t0] =
                __floats2half2_rn(ua[c], ub[c]);
        }
    }
}

// ---------------- batched component GEMMs ----------------
__device__ __forceinline__ uint32_t smem_u32(const void* p) {
    uint32_t a;
    asm("{ .reg .u64 t; cvta.to.shared.u64 t, %1; cvt.u32.u64 %0, t; }" : "=r"(a) : "l"(p));
    return a;
}
__device__ __forceinline__ void cp16(uint32_t dst, const void* src) {
    asm volatile("cp.async.cg.shared.global [%0], [%1], 16;" :: "r"(dst), "l"(src) : "memory");
}
__device__ __forceinline__ void cp_commit() {
    asm volatile("cp.async.commit_group;" ::: "memory");
}
__device__ __forceinline__ void ldsm_x4(uint32_t* r, uint32_t a) {
    asm volatile("ldmatrix.sync.aligned.m8n8.x4.shared.b16 {%0,%1,%2,%3}, [%4];"
                 : "=r"(r[0]), "=r"(r[1]), "=r"(r[2]), "=r"(r[3]) : "r"(a));
}
__device__ __forceinline__ void ldsm_x2t(uint32_t* r, uint32_t a) {
    asm volatile("ldmatrix.sync.aligned.m8n8.x2.trans.shared.b16 {%0,%1}, [%2];"
                 : "=r"(r[0]), "=r"(r[1]) : "r"(a));
}
__device__ __forceinline__ void mma16816(float* d, const uint32_t* a, const uint32_t* b) {
    asm volatile(
        "mma.sync.aligned.m16n8k16.row.col.f32.f16.f16.f32 "
        "{%0,%1,%2,%3}, {%4,%5,%6,%7}, {%8,%9}, {%0,%1,%2,%3};"
        : "+f"(d[0]), "+f"(d[1]), "+f"(d[2]), "+f"(d[3])
        : "r"(a[0]), "r"(a[1]), "r"(a[2]), "r"(a[3]), "r"(b[0]), "r"(b[1]));
}

#define A_BYTES 10240           // 128 rows * 80B (64 used)
#define B_BYTES 7680            // 32 rows * 240B (224 used = 112 tiles fp16)
#define STAGE_BYTES (A_BYTES + B_BYTES)   // 17920
#define NBUF 4
#define SMEM_SZ (NBUF * STAGE_BYTES)      // 71680
#define NSTAGE 8                // K = 256 = 8 * 32

__device__ __forceinline__ void load_stage(int kc, uint32_t sbase, int tid,
                                           int k, int coh, int tb) {
    const __half* wsrc = g_Wt + (((size_t)(k * 2 + coh) * 8 + kc) << 12);
    // A: 512 x 16B contiguous
#pragma unroll
    for (int v = tid; v < 512; v += 256) {
        cp16(sbase + (v >> 2) * 80 + (v & 3) * 16, (const char*)wsrc + v * 16);
    }
    // B: 448 x 16B — rows are ci, 112 tiles each
    uint32_t bbase = sbase + A_BYTES;
    const __half* usrc = g_U + (size_t)(k * C + kc * 32) * NTILE + tb * 112;
    for (int v = tid; v < 448; v += 256) {
        int row = v / 14;
        int cv  = v - row * 14;
        cp16(bbase + row * 240 + cv * 16,
             (const char*)(usrc + (size_t)row * NTILE) + cv * 16);
    }
}

__global__ __launch_bounds__(256, 2) void wino_gemm_kernel() {
    extern __shared__ __align__(16) unsigned char smbuf[];
    const uint32_t sb = smem_u32(smbuf);
    const int tid  = threadIdx.x;
    const int lane = tid & 31;
    const int wid  = tid >> 5;
    const int wm   = wid & 3;       // 4 M-warps x 32 co
    const int wn   = wid >> 2;      // 2 N-warps x 56 tiles
    const int tb   = blockIdx.x;    // 0..111 (112-tile blocks)
    const int k    = blockIdx.y >> 1;
    const int coh  = blockIdx.y & 1;

    float acc[2][7][4];
#pragma unroll
    for (int m = 0; m < 2; ++m)
#pragma unroll
        for (int n = 0; n < 7; ++n)
#pragma unroll
            for (int q = 0; q < 4; ++q) acc[m][n][q] = 0.0f;

    load_stage(0, sb, tid, k, coh, tb);
    cp_commit();
    load_stage(1, sb + STAGE_BYTES, tid, k, coh, tb);
    cp_commit();
    load_stage(2, sb + 2 * STAGE_BYTES, tid, k, coh, tb);
    cp_commit();

    for (int i = 0; i < NSTAGE; ++i) {
        asm volatile("cp.async.wait_group 2;" ::: "memory");
        __syncthreads();
        if (i + 3 < NSTAGE)
            load_stage(i + 3, sb + ((i + 3) & 3) * STAGE_BYTES, tid, k, coh, tb);
        cp_commit();   // one group per iteration (possibly empty)

        const uint32_t As = sb + (i & 3) * STAGE_BYTES;
        const uint32_t Bs = As + A_BYTES;
        uint32_t aA[2], aB[7];
#pragma unroll
        for (int m = 0; m < 2; ++m)
            aA[m] = As + (wm * 32 + m * 16 + (lane & 15)) * 80 + (lane >> 4) * 16;
#pragma unroll
        for (int n = 0; n < 7; ++n)
            aB[n] = Bs + (lane & 15) * 240 + wn * 112 + n * 16;

#pragma unroll
        for (int ks = 0; ks < 2; ++ks) {
            uint32_t a[2][4], b[7][2];
#pragma unroll
            for (int m = 0; m < 2; ++m) ldsm_x4(a[m], aA[m] + ks * 32);
#pragma unroll
            for (int n = 0; n < 7; ++n) ldsm_x2t(b[n], aB[n] + ks * 16 * 240);
#pragma unroll
            for (int m = 0; m < 2; ++m)
#pragma unroll
                for (int n = 0; n < 7; ++n) mma16816(acc[m][n], a[m], b[n]);
        }
    }

    // epilogue: write M_k fp16
    const int rq = lane >> 2;
    const int cq = (lane & 3) * 2;
#pragma unroll
    for (int m = 0; m < 2; ++m) {
#pragma unroll
        for (int n = 0; n < 7; ++n) {
            int co  = coh * 128 + wm * 32 + m * 16 + rq;
            int col = wn * 56 + n * 8 + cq;
            size_t base = (size_t)(k * C + co) * NTILE + tb * 112 + col;
            *(__half2*)&g_M[base] =
                __floats2half2_rn(acc[m][n][0], acc[m][n][1]);
            *(__half2*)&g_M[base + 8ull * NTILE] =
                __floats2half2_rn(acc[m][n][2], acc[m][n][3]);
        }
    }
}

// ---------------- inverse transform: y = A^T M A, 2 tiles per thread --------
__global__ void wino_out_kernel(float* __restrict__ out) {
    int p = blockIdx.x * 128 + threadIdx.x;    // 0..6271 tile-pairs, grid.x = 49
    int co = blockIdx.y;
    int ty = p / 56, px = p - ty * 56;
    size_t t0 = (size_t)ty * TW + px * 2;
    float ma[4][4], mb[4][4];
#pragma unroll
    for (int k = 0; k < 16; ++k) {
        __half2 v = *(const __half2*)&g_M[(size_t)(k * C + co) * NTILE + t0];
        float2 f = __half22float2(v);
        ma[k >> 2][k & 3] = f.x;
        mb[k >> 2][k & 3] = f.y;
    }
    float4 row0, row1;
    {
        float r0[4], r1[4];
#pragma unroll
        for (int c = 0; c < 4; ++c) {
            r0[c] = ma[0][c] + ma[1][c] + ma[2][c];
            r1[c] = ma[1][c] - ma[2][c] - ma[3][c];
        }
        row0.x = r0[0] + r0[1] + r0[2];
        row0.y = r0[1] - r0[2] - r0[3];
        row1.x = r1[0] + r1[1] + r1[2];
        row1.y = r1[1] - r1[2] - r1[3];
    }
    {
        float r0[4], r1[4];
#pragma unroll
        for (int c = 0; c < 4; ++c) {
            r0[c] = mb[0][c] + mb[1][c] + mb[2][c];
            r1[c] = mb[1][c] - mb[2][c] - mb[3][c];
        }
        row0.z = r0[0] + r0[1] + r0[2];
        row0.w = r0[1] - r0[2] - r0[3];
        row1.z = r1[0] + r1[1] + r1[2];
        row1.w = r1[1] - r1[2] - r1[3];
    }
    float* pp = out + ((size_t)co * H + 2 * ty) * W + 4 * px;
    *(float4*)pp       = row0;
    *(float4*)(pp + W) = row1;
}

extern "C" void kernel_launch(void* const* d_in, const int* in_sizes, int n_in,
                              void* d_out, int out_size) {
    const float* x = (const float*)d_in[0];   // [1,256,224,224]
    const float* w = (const float*)d_in[1];   // [256,256,3,3]
    float* out = (float*)d_out;               // [256,224,224]
    (void)in_sizes; (void)n_in; (void)out_size;

    wino_w_kernel<<<(C * C + 255) / 256, 256>>>(w);
    wino_in_kernel<<<dim3(49, C), 128>>>(x);

    cudaFuncSetAttribute(wino_gemm_kernel,
                         cudaFuncAttributeMaxDynamicSharedMemorySize, SMEM_SZ);
    wino_gemm_kernel<<<dim3(TW, 32), 256, SMEM_SZ>>>();
    wino_out_kernel<<<dim3(49, C), 128>>>(out);
}